// round 8
// baseline (speedup 1.0000x reference)
#include <cuda_runtime.h>
#include <cstdint>

#define NPTS 4096
#define DDIM 64
#define LDT 68      // A/B smem stride (floats), conflict-free fragment loads
#define SLD 132     // staging stride: conflict-free transpose staging (banks 8t+g)
#define NBLOCKS 272 // pair-tile blocks
#define NDUTY 256   // bandwidth-reduction duty CTAs (16 rows each)

// ---------------- device scratch (zero-init; counters self-reset) ----------------
__device__ float g_partial_sq[NDUTY];
__device__ float g_partial_col[NDUTY][64];
__device__ float g_c;
__device__ int   g_arrive = 0;
__device__ int   g_done   = 0;
__device__ unsigned int g_flag = 0;

__device__ __forceinline__ uint32_t to_tf32(float f) {
    uint32_t o; asm("cvt.rna.tf32.f32 %0, %1;" : "=r"(o) : "f"(f)); return o;
}

// tf32 mma over one 128x128 tile: As/Bs [128][LDT]
__device__ __forceinline__ void mma_tile(const float* As, const float* Bs,
                                         int warpRow, int warpCol, int g, int t,
                                         float acc[2][8][4]) {
#pragma unroll
    for (int m = 0; m < 2; m++)
#pragma unroll
        for (int n = 0; n < 8; n++)
#pragma unroll
            for (int j = 0; j < 4; j++) acc[m][n][j] = 0.f;
#pragma unroll
    for (int ks = 0; ks < 8; ks++) {
        const int k0 = ks << 3;
        uint32_t af[2][4], bf[8][2];
#pragma unroll
        for (int m = 0; m < 2; m++) {
            const float* ap = As + (size_t)(warpRow + (m << 4) + g) * LDT + k0 + t;
            af[m][0] = __float_as_uint(ap[0]);
            af[m][1] = __float_as_uint(ap[8 * LDT]);
            af[m][2] = __float_as_uint(ap[4]);
            af[m][3] = __float_as_uint(ap[8 * LDT + 4]);
        }
#pragma unroll
        for (int n = 0; n < 8; n++) {
            const float* bp = Bs + (size_t)(warpCol + (n << 3) + g) * LDT + k0 + t;
            bf[n][0] = __float_as_uint(bp[0]);
            bf[n][1] = __float_as_uint(bp[4]);
        }
#pragma unroll
        for (int m = 0; m < 2; m++)
#pragma unroll
            for (int n = 0; n < 8; n++) {
                asm volatile(
                    "mma.sync.aligned.m16n8k8.row.col.f32.tf32.tf32.f32 "
                    "{%0,%1,%2,%3}, {%4,%5,%6,%7}, {%8,%9}, {%0,%1,%2,%3};"
                    : "+f"(acc[m][n][0]), "+f"(acc[m][n][1]),
                      "+f"(acc[m][n][2]), "+f"(acc[m][n][3])
                    : "r"(af[m][0]), "r"(af[m][1]), "r"(af[m][2]), "r"(af[m][3]),
                      "r"(bf[n][0]), "r"(bf[n][1]));
            }
    }
}

__device__ __forceinline__ void epilogue_tile(float acc[2][8][4],
                                              const float* sqa, const float* sqb,
                                              float cc, float* out,
                                              int rowBase, int colBase,
                                              int warpRow, int warpCol, int g, int t,
                                              bool stage, float* stg) {
    const float c2 = 2.f * cc;
#pragma unroll
    for (int m = 0; m < 2; m++) {
        const int r0 = warpRow + (m << 4) + g;
        const float u0 = -cc * sqa[r0], u1 = -cc * sqa[r0 + 8];
#pragma unroll
        for (int n = 0; n < 8; n++) {
            const int c0 = warpCol + (n << 3) + (t << 1);
            const float v0 = -cc * sqb[c0], v1 = -cc * sqb[c0 + 1];
            const float ws[4] = { u0 + v0, u0 + v1, u1 + v0, u1 + v1 };
            float r[4];
#pragma unroll
            for (int j = 0; j < 4; j++) {
                float y = fminf(fmaf(c2, acc[m][n][j], ws[j]), 0.f);
                float e;
                asm("ex2.approx.ftz.f32 %0, %1;" : "=f"(e) : "f"(y));
                float e2 = e * e, e4 = e2 * e2, e8 = e4 * e4, e16 = e8 * e8;
                r[j] = e + e2 + e4 + e8 + e16;
            }
            float* o0 = out + (size_t)(rowBase + r0) * NPTS + colBase + c0;
            float* o1 = out + (size_t)(rowBase + r0 + 8) * NPTS + colBase + c0;
            *(float2*)o0 = make_float2(r[0], r[1]);
            *(float2*)o1 = make_float2(r[2], r[3]);
            if (stage) {
                stg[(c0)     * SLD + r0]     = r[0];
                stg[(c0 + 1) * SLD + r0]     = r[1];
                stg[(c0)     * SLD + r0 + 8] = r[2];
                stg[(c0 + 1) * SLD + r0 + 8] = r[3];
            }
        }
    }
}

__device__ __forceinline__ void mirror_tile(const float* stg, float* out,
                                            int rowBase, int colBase,
                                            int wid, int lane) {
    const int c_off = lane >> 3, r_off = (lane & 7) << 2;
#pragma unroll
    for (int i = 0; i < 16; i++) {
        int c = (wid << 4) + ((i & 3) << 2) + c_off;
        int r = ((i >> 2) << 5) + r_off;
        float4 v = *(const float4*)&stg[c * SLD + r];
        *(float4*)(out + (size_t)(colBase + c) * NPTS + rowBase + r) = v;
    }
}

__global__ __launch_bounds__(256, 2)
void rbf_fused_kernel(const float* __restrict__ X, float* __restrict__ out) {
    extern __shared__ float smem[];
    float* As  = smem;                  // [128][LDT]
    float* B1s = smem + 128 * LDT;
    float* B2s = smem + 2 * 128 * LDT;
    float* stg = smem + 128 * LDT;      // aliases B1s+B2s
    __shared__ float sqa[128], sqb1[128], sqb2[128];
    __shared__ float red[256];
    __shared__ float colp[8][64];
    __shared__ float red2[64];
    __shared__ float s_c;
    __shared__ int   s_last;

    const int tid = threadIdx.x;
    const int wid = tid >> 5, lane = tid & 31;
    const int bid = blockIdx.x;

    // pair-tile decode: bid -> (bi, p); tiles (bi, 2p) [if valid] and (bi, 2p+1)
    int bi = 0, rr = bid;
    while (rr >= 16 - (bi >> 1)) { rr -= 16 - (bi >> 1); bi++; }
    const int p = (bi >> 1) + rr;
    const bool two = (2 * p >= bi);
    const int bj1 = two ? 2 * p : 2 * p + 1;
    const int bj2 = 2 * p + 1;
    const bool diag1 = (bj1 == bi);
    const int rowBase = bi << 7, colBase1 = bj1 << 7, colBase2 = bj2 << 7;

    // ======= prefetch A + B1 tiles into registers (hides fill latency under duty) =======
    float4 pa[8], pb[8];
#pragma unroll
    for (int i = 0; i < 8; i++) {
        int idx = tid + (i << 8);
        int r = idx >> 4, f = idx & 15;
        pa[i] = *(const float4*)(X + (size_t)(rowBase + r) * DDIM + (f << 2));
        pb[i] = *(const float4*)(X + (size_t)(colBase1 + r) * DDIM + (f << 2));
    }

    // ================= phase 0: bandwidth duty, 16 rows per duty CTA =================
    if (bid < NDUTY) {
        const int row = (bid << 4) + (tid >> 4);
        const int f = tid & 15;
        float4 d = *(const float4*)(X + (size_t)row * DDIM + (f << 2));
        float s = d.x * d.x + d.y * d.y + d.z * d.z + d.w * d.w;
#pragma unroll
        for (int off = 16; off >= 1; off >>= 1)
            s += __shfl_xor_sync(0xffffffffu, s, off);
        if (lane == 0) red[wid] = s;

        // column partials: xor-16 sums the warp's two rows; lanes 0..15 hold f=lane
        d.x += __shfl_xor_sync(0xffffffffu, d.x, 16);
        d.y += __shfl_xor_sync(0xffffffffu, d.y, 16);
        d.z += __shfl_xor_sync(0xffffffffu, d.z, 16);
        d.w += __shfl_xor_sync(0xffffffffu, d.w, 16);
        if (lane < 16) {
            colp[wid][lane * 4 + 0] = d.x;
            colp[wid][lane * 4 + 1] = d.y;
            colp[wid][lane * 4 + 2] = d.z;
            colp[wid][lane * 4 + 3] = d.w;
        }
        __syncthreads();
        if (wid == 0) {
            float x = (lane < 8) ? red[lane] : 0.f;
#pragma unroll
            for (int off = 4; off >= 1; off >>= 1)
                x += __shfl_xor_sync(0xffffffffu, x, off);
            if (lane == 0) g_partial_sq[bid] = x;
        }
        if (tid < 64) {
            float t = 0.f;
#pragma unroll
            for (int w = 0; w < 8; w++) t += colp[w][tid];
            g_partial_col[bid][tid] = t;
        }
        __threadfence();
        if (tid == 0) {
            int r = atomicAdd(&g_arrive, 1);
            s_last = (r == NDUTY - 1);
        }
        __syncthreads();

        if (s_last) {
            // deterministic finalize (runs on one CTA; hidden under others' MMA)
            red[tid] = g_partial_sq[tid];
            {
                const int c = tid & 63, q = tid >> 6;
                float cp = 0.f;
#pragma unroll 8
                for (int b = 0; b < 64; b++) cp += g_partial_col[q * 64 + b][c];
                colp[q][c] = cp;   // colp flat: 8x64 >= 4x64
            }
            __syncthreads();
            if (tid < 64) {
                float cs = colp[0][tid] + colp[1][tid] + colp[2][tid] + colp[3][tid];
                red2[tid] = cs * cs;
            }
            __syncthreads();
#pragma unroll
            for (int off = 128; off > 0; off >>= 1) {
                if (tid < off) {
                    red[tid] += red[tid + off];
                    if (off <= 32) red2[tid] += red2[tid + off];
                }
                __syncthreads();
            }
            if (tid == 0) {
                // sum(L2) = 2*N*sum(||xi||^2) - 2*||sum xi||^2 (clamp negligible)
                float bwsum = 2.f * (float)NPTS * red[0] - 2.f * red2[0];
                float bw = bwsum / ((float)NPTS * (float)(NPTS - 1));
                g_c = 1.4426950408889634f / (4.f * bw);
                __threadfence();
                asm volatile("st.release.gpu.b32 [%0], %1;" :: "l"(&g_flag), "r"(1u) : "memory");
            }
        }
        __syncthreads();
    }

    // ================= phase 1: fill A + B1 smem from prefetched regs + norms =================
#pragma unroll
    for (int i = 0; i < 8; i++) {
        int idx = tid + (i << 8);
        int r = idx >> 4, f = idx & 15;
        float4 va = pa[i], vb = pb[i];
        float da = va.x * va.x + va.y * va.y + va.z * va.z + va.w * va.w;
        float db = vb.x * vb.x + vb.y * vb.y + vb.z * vb.z + vb.w * vb.w;
#pragma unroll
        for (int stp = 1; stp <= 8; stp <<= 1) {
            da += __shfl_xor_sync(0xffffffffu, da, stp);
            db += __shfl_xor_sync(0xffffffffu, db, stp);
        }
        if ((lane & 15) == 0) { sqa[r] = da; sqb1[r] = db; }
        uint4 ta = { to_tf32(va.x), to_tf32(va.y), to_tf32(va.z), to_tf32(va.w) };
        uint4 tb = { to_tf32(vb.x), to_tf32(vb.y), to_tf32(vb.z), to_tf32(vb.w) };
        *(uint4*)(As + r * LDT + (f << 2)) = ta;
        *(uint4*)(B1s + r * LDT + (f << 2)) = tb;
    }
    __syncthreads();

    // ================= phase 2: MMA tile 1 =================
    const int g = lane >> 2, t = lane & 3;
    const int warpRow = (wid & 3) << 5;
    const int warpCol = (wid >> 2) << 6;

    float acc[2][8][4];
    mma_tile(As, B1s, warpRow, warpCol, g, t, acc);

    // prefetch B2 into registers (latency hides under spin + epilogue1)
    if (two) {
#pragma unroll
        for (int i = 0; i < 8; i++) {
            int idx = tid + (i << 8);
            int r = idx >> 4, f = idx & 15;
            pb[i] = *(const float4*)(X + (size_t)(colBase2 + r) * DDIM + (f << 2));
        }
    }

    // ================= phase 3: wait for g_c (usually already set) =================
    if (tid == 0) {
        unsigned int f;
        do {
            asm volatile("ld.acquire.gpu.b32 %0, [%1];" : "=r"(f) : "l"(&g_flag) : "memory");
        } while (f == 0);
        s_c = g_c;
    }
    __syncthreads();   // also: all MMA1 reads complete before stg writes
    const float cc = s_c;

    // ================= phase 4: epilogue tile 1 (+ mirror if offdiag) =================
    epilogue_tile(acc, sqa, sqb1, cc, out, rowBase, colBase1,
                  warpRow, warpCol, g, t, !diag1, stg);
    if (!diag1) {
        __syncthreads();
        mirror_tile(stg, out, rowBase, colBase1, wid, lane);
    }

    // ================= phase 5: tile 2 =================
    if (two) {
        __syncthreads();   // mirror1 stg reads done before B2s overwrite
#pragma unroll
        for (int i = 0; i < 8; i++) {
            int idx = tid + (i << 8);
            int r = idx >> 4, f = idx & 15;
            float4 vb = pb[i];
            float db = vb.x * vb.x + vb.y * vb.y + vb.z * vb.z + vb.w * vb.w;
#pragma unroll
            for (int stp = 1; stp <= 8; stp <<= 1)
                db += __shfl_xor_sync(0xffffffffu, db, stp);
            if ((lane & 15) == 0) sqb2[r] = db;
            uint4 tb = { to_tf32(vb.x), to_tf32(vb.y), to_tf32(vb.z), to_tf32(vb.w) };
            *(uint4*)(B2s + r * LDT + (f << 2)) = tb;
        }
        __syncthreads();

        mma_tile(As, B2s, warpRow, warpCol, g, t, acc);
        __syncthreads();   // all B2s reads complete before stg writes

        epilogue_tile(acc, sqa, sqb2, cc, out, rowBase, colBase2,
                      warpRow, warpCol, g, t, true, stg);
        __syncthreads();
        mirror_tile(stg, out, rowBase, colBase2, wid, lane);
    }

    // ================= phase 6: last CTA resets counters for next replay =================
    if (tid == 0) {
        int d = atomicAdd(&g_done, 1);
        if (d == NBLOCKS - 1) {
            g_arrive = 0;
            g_done = 0;
            asm volatile("st.relaxed.gpu.b32 [%0], %1;" :: "l"(&g_flag), "r"(0u) : "memory");
        }
    }
}

// ---------------- launch ----------------
extern "C" void kernel_launch(void* const* d_in, const int* in_sizes, int n_in,
                              void* d_out, int out_size) {
    const float* X = (const float*)d_in[0];
    float* out = (float*)d_out;

    const int smem_bytes = 3 * 128 * LDT * sizeof(float);   // 104448
    cudaFuncSetAttribute(rbf_fused_kernel, cudaFuncAttributeMaxDynamicSharedMemorySize, smem_bytes);

    rbf_fused_kernel<<<NBLOCKS, 256, smem_bytes>>>(X, out);
}